// round 2
// baseline (speedup 1.0000x reference)
#include <cuda_runtime.h>
#include <math.h>

#define BATCH     32768
#define IN_DIM    64
#define NUM_BINS  10
#define EMBED_DIM 64
#define NTHRESH   9

// K1 geometry: x as float4[BATCH*16]. T threads, NV/T = 4 exact iterations.
#define K1_BLOCKS  512
#define K1_THREADS 256
#define NPART      K1_BLOCKS
#define NV         (BATCH * 16)          // 524288 float4s
#define K1_T       (K1_BLOCKS * K1_THREADS)  // 131072 -> exactly 4 iters

// ---- scratch (device globals; no allocation allowed) ----
__device__ float g_pmin[NPART * IN_DIM];
__device__ float g_pmax[NPART * IN_DIM];
__device__ float g_mn[IN_DIM];
__device__ float g_dn[IN_DIM];
__device__ float g_bins[NUM_BINS];
__device__ float g_M[NUM_BINS * EMBED_DIM];   // M[k][f] = embed[k] . W[f]

// ================= Kernel 1: per-column partial min/max (float4, MLP=4) ===
// Thread t's float4 index walks t, t+T, t+2T, t+3T. Since T % 16 == 0, the
// column group (t % 16)*4 .. +3 is invariant -> 4 running min/max registers.
__global__ void __launch_bounds__(K1_THREADS) k_minmax(const float4* __restrict__ x4) {
    const int tid = blockIdx.x * K1_THREADS + threadIdx.x;

    // 4 independent 128-bit loads in flight
    float4 v0 = x4[tid];
    float4 v1 = x4[tid + K1_T];
    float4 v2 = x4[tid + 2 * K1_T];
    float4 v3 = x4[tid + 3 * K1_T];

    float mn0 = fminf(fminf(v0.x, v1.x), fminf(v2.x, v3.x));
    float mn1 = fminf(fminf(v0.y, v1.y), fminf(v2.y, v3.y));
    float mn2 = fminf(fminf(v0.z, v1.z), fminf(v2.z, v3.z));
    float mn3 = fminf(fminf(v0.w, v1.w), fminf(v2.w, v3.w));
    float mx0 = fmaxf(fmaxf(v0.x, v1.x), fmaxf(v2.x, v3.x));
    float mx1 = fmaxf(fmaxf(v0.y, v1.y), fmaxf(v2.y, v3.y));
    float mx2 = fmaxf(fmaxf(v0.z, v1.z), fmaxf(v2.z, v3.z));
    float mx3 = fmaxf(fmaxf(v0.w, v1.w), fmaxf(v2.w, v3.w));

    // warp-level: lane and lane+16 share a column group
    #pragma unroll
    for (int q = 0; q < 1; q++) { }  // (no-op; keep structure simple)
    mn0 = fminf(mn0, __shfl_down_sync(0xffffffffu, mn0, 16));
    mn1 = fminf(mn1, __shfl_down_sync(0xffffffffu, mn1, 16));
    mn2 = fminf(mn2, __shfl_down_sync(0xffffffffu, mn2, 16));
    mn3 = fminf(mn3, __shfl_down_sync(0xffffffffu, mn3, 16));
    mx0 = fmaxf(mx0, __shfl_down_sync(0xffffffffu, mx0, 16));
    mx1 = fmaxf(mx1, __shfl_down_sync(0xffffffffu, mx1, 16));
    mx2 = fmaxf(mx2, __shfl_down_sync(0xffffffffu, mx2, 16));
    mx3 = fmaxf(mx3, __shfl_down_sync(0xffffffffu, mx3, 16));

    // lanes 0..15 of each of 8 warps hold group results -> shared reduce
    __shared__ float smn[8][16][4];
    __shared__ float smx[8][16][4];
    const int lane = threadIdx.x & 31;
    const int wrp  = threadIdx.x >> 5;
    if (lane < 16) {
        smn[wrp][lane][0] = mn0; smn[wrp][lane][1] = mn1;
        smn[wrp][lane][2] = mn2; smn[wrp][lane][3] = mn3;
        smx[wrp][lane][0] = mx0; smx[wrp][lane][1] = mx1;
        smx[wrp][lane][2] = mx2; smx[wrp][lane][3] = mx3;
    }
    __syncthreads();
    if (threadIdx.x < IN_DIM) {
        const int g = threadIdx.x >> 2;   // column group 0..15
        const int q = threadIdx.x & 3;    // slot in group
        float a =  INFINITY, b = -INFINITY;
        #pragma unroll
        for (int w = 0; w < 8; w++) {
            a = fminf(a, smn[w][g][q]);
            b = fmaxf(b, smx[w][g][q]);
        }
        g_pmin[blockIdx.x * IN_DIM + threadIdx.x] = a;
        g_pmax[blockIdx.x * IN_DIM + threadIdx.x] = b;
    }
}

// ====== Kernel 2: finalize min/max (parallel), bins, M = embed@W^T ======
__global__ void __launch_bounds__(1024) k_small(const float* __restrict__ logits,
                                                const float* __restrict__ embed,
                                                const float* __restrict__ W) {
    const int tid = threadIdx.x;

    // ---- bins (thread 0): replicate the reference f32 op sequence ----
    if (tid == 0) {
        float l[NUM_BINS];
        float m = -INFINITY;
        #pragma unroll
        for (int i = 0; i < NUM_BINS; i++) { l[i] = logits[i]; m = fmaxf(m, l[i]); }
        float e[NUM_BINS];
        float s = 0.f;
        #pragma unroll
        for (int i = 0; i < NUM_BINS; i++) {
            e[i] = (float)exp((double)(l[i] - m));   // correctly-rounded f32 exp
            s += e[i];
        }
        float cum = 0.f;
        #pragma unroll
        for (int i = 0; i < NUM_BINS; i++) {
            cum += __fdiv_rn(e[i], s);               // IEEE div under fast-math
            g_bins[i] = cum;
        }
    }

    // ---- min/max finalize: 16 threads per column, NPART=512 partials ----
    {
        const int col = tid >> 4;   // 0..63
        const int sub = tid & 15;   // 0..15
        float mn =  INFINITY, mx = -INFINITY;
        for (int i = sub; i < NPART; i += 16) {
            mn = fminf(mn, g_pmin[i * IN_DIM + col]);
            mx = fmaxf(mx, g_pmax[i * IN_DIM + col]);
        }
        #pragma unroll
        for (int d = 8; d >= 1; d >>= 1) {
            mn = fminf(mn, __shfl_xor_sync(0xffffffffu, mn, d));
            mx = fmaxf(mx, __shfl_xor_sync(0xffffffffu, mx, d));
        }
        if (sub == 0) {
            g_mn[col] = mn;
            g_dn[col] = (mx - mn) + 1e-6f;
        }
    }

    // ---- M[k][f] = embed[k] . W[f]  (640 of 1024 threads) ----
    if (tid < NUM_BINS * EMBED_DIM) {
        const int k = tid / EMBED_DIM;
        const int f = tid % EMBED_DIM;
        const float* er = embed + k * EMBED_DIM;
        const float* wr = W + f * EMBED_DIM;
        float s = 0.f;
        #pragma unroll 8
        for (int e2 = 0; e2 < EMBED_DIM; e2++) s = fmaf(er[e2], wr[e2], s);
        g_M[tid] = s;
    }
}

// ================= Kernel 3: main (2 rows per warp, single iteration) =====
// out[b,f] = 64*(M[0][f] + bias[f]) + sum_{k=1..9} c_k * (M[k][f]-M[k-1][f])
// c_k via warp ballots. 2048 blocks x 8 warps = 16384 warps = BATCH/2.
#define K3_BLOCKS 2048
__global__ void __launch_bounds__(256) k_main(const float* __restrict__ x,
                                              const float* __restrict__ bias,
                                              float* __restrict__ out) {
    const int lane = threadIdx.x & 31;
    const int w    = (blockIdx.x * 256 + threadIdx.x) >> 5;   // 0..16383
    const int r0   = w * 2;
    const int r1   = r0 + 1;

    const int c0 = lane * 2;
    const int c1 = c0 + 1;

    const float2* __restrict__ x2   = (const float2*)x;
    float2* __restrict__       out2 = (float2*)out;

    // issue both row loads up front (MLP = 2 x 64-bit)
    const float2 xa = x2[r0 * 32 + lane];
    const float2 xb = x2[r1 * 32 + lane];

    const float mn0 = g_mn[c0], mn1 = g_mn[c1];
    const float dn0 = g_dn[c0], dn1 = g_dn[c1];

    float bins[NTHRESH];
    #pragma unroll
    for (int k = 0; k < NTHRESH; k++) bins[k] = g_bins[k];

    const float base0 = 64.f * (g_M[c0] + bias[c0]);
    const float base1 = 64.f * (g_M[c1] + bias[c1]);

    float D0[NTHRESH], D1[NTHRESH];
    #pragma unroll
    for (int k = 0; k < NTHRESH; k++) {
        D0[k] = g_M[(k + 1) * EMBED_DIM + c0] - g_M[k * EMBED_DIM + c0];
        D1[k] = g_M[(k + 1) * EMBED_DIM + c1] - g_M[k * EMBED_DIM + c1];
    }

    // exact same f32 op sequence as reference: sub then IEEE divide
    const float a_xn0 = __fdiv_rn(xa.x - mn0, dn0);
    const float a_xn1 = __fdiv_rn(xa.y - mn1, dn1);
    const float b_xn0 = __fdiv_rn(xb.x - mn0, dn0);
    const float b_xn1 = __fdiv_rn(xb.y - mn1, dn1);

    float a0 = base0, a1 = base1;
    float b0 = base0, b1 = base1;
    #pragma unroll
    for (int k = 0; k < NTHRESH; k++) {
        unsigned am0 = __ballot_sync(0xffffffffu, a_xn0 > bins[k]);
        unsigned am1 = __ballot_sync(0xffffffffu, a_xn1 > bins[k]);
        unsigned bm0 = __ballot_sync(0xffffffffu, b_xn0 > bins[k]);
        unsigned bm1 = __ballot_sync(0xffffffffu, b_xn1 > bins[k]);
        float fa = (float)(__popc(am0) + __popc(am1));
        float fb = (float)(__popc(bm0) + __popc(bm1));
        a0 = fmaf(fa, D0[k], a0);
        a1 = fmaf(fa, D1[k], a1);
        b0 = fmaf(fb, D0[k], b0);
        b1 = fmaf(fb, D1[k], b1);
    }
    out2[r0 * 32 + lane] = make_float2(a0, a1);
    out2[r1 * 32 + lane] = make_float2(b0, b1);
}

extern "C" void kernel_launch(void* const* d_in, const int* in_sizes, int n_in,
                              void* d_out, int out_size) {
    const float* x      = (const float*)d_in[0];
    const float* logits = (const float*)d_in[1];
    const float* embed  = (const float*)d_in[2];
    const float* W      = (const float*)d_in[3];
    const float* bias   = (const float*)d_in[4];
    float* out          = (float*)d_out;

    k_minmax<<<K1_BLOCKS, K1_THREADS>>>((const float4*)x);
    k_small<<<1, 1024>>>(logits, embed, W);
    k_main<<<K3_BLOCKS, 256>>>(x, bias, out);
}

// round 3
// speedup vs baseline: 1.0411x; 1.0411x over previous
#include <cuda_runtime.h>
#include <math.h>

#define BATCH     32768
#define IN_DIM    64
#define NUM_BINS  10
#define EMBED_DIM 64
#define NTHRESH   9

#define GRID  592                 // 148 SMs * 4 blocks -> all co-resident
#define TPB   256
#define MMB   591                 // blocks 0..590 do min/max; block 591 does bins+M
#define T1    (MMB * TPB)         // 151296 threads; %16==0 keeps col-group invariant
#define NV    (BATCH * 16)        // x as float4 count
#define NWARP (GRID * 8)          // 4736 phase-2 warps

// ---- scratch (device globals; no allocation allowed) ----
__device__ float g_pmin[MMB * IN_DIM];
__device__ float g_pmax[MMB * IN_DIM];
__device__ float g_mn[IN_DIM];
__device__ float g_dn[IN_DIM];
__device__ float g_bins[NTHRESH];
__device__ float g_M[NUM_BINS * EMBED_DIM];   // M[k][f] = embed[k] . W[f]
__device__ int       g_count;                 // arrival counter (reset each launch)
__device__ unsigned  g_release;               // epoch counter (monotonic across replays)

__global__ void __launch_bounds__(TPB, 4)
dybem_fused(const float*  __restrict__ x,
            const float*  __restrict__ logits,
            const float*  __restrict__ embed,
            const float*  __restrict__ W,
            const float*  __restrict__ bias,
            float*        __restrict__ out) {
    const int tid  = threadIdx.x;
    const int lane = tid & 31;
    const int wrp  = tid >> 5;
    const int b    = blockIdx.x;

    __shared__ unsigned s_snap;
    __shared__ int      s_ticket;
    __shared__ float smn[8][16][4];
    __shared__ float smx[8][16][4];
    __shared__ float rmn[4][IN_DIM];
    __shared__ float rmx[4][IN_DIM];

    // Epoch snapshot BEFORE any work (release for this launch can only
    // happen after this block arrives, which is after this read).
    if (tid == 0) s_snap = *(volatile unsigned*)&g_release;
    __syncthreads();

    // ================= PHASE 1 =================
    if (b < MMB) {
        // --- per-column-group min/max over x (float4, grid-stride) ---
        const float4* __restrict__ x4 = (const float4*)x;
        const int tg = b * TPB + tid;
        float mn0 =  INFINITY, mn1 =  INFINITY, mn2 =  INFINITY, mn3 =  INFINITY;
        float mx0 = -INFINITY, mx1 = -INFINITY, mx2 = -INFINITY, mx3 = -INFINITY;
        // T1 % 16 == 0 so (idx % 16) == (tid % 16) is loop-invariant
        for (int idx = tg; idx < NV; idx += T1) {
            float4 v = x4[idx];
            mn0 = fminf(mn0, v.x); mx0 = fmaxf(mx0, v.x);
            mn1 = fminf(mn1, v.y); mx1 = fmaxf(mx1, v.y);
            mn2 = fminf(mn2, v.z); mx2 = fmaxf(mx2, v.z);
            mn3 = fminf(mn3, v.w); mx3 = fmaxf(mx3, v.w);
        }
        // lanes l and l+16 share a column group (tid%16)
        mn0 = fminf(mn0, __shfl_down_sync(0xffffffffu, mn0, 16));
        mn1 = fminf(mn1, __shfl_down_sync(0xffffffffu, mn1, 16));
        mn2 = fminf(mn2, __shfl_down_sync(0xffffffffu, mn2, 16));
        mn3 = fminf(mn3, __shfl_down_sync(0xffffffffu, mn3, 16));
        mx0 = fmaxf(mx0, __shfl_down_sync(0xffffffffu, mx0, 16));
        mx1 = fmaxf(mx1, __shfl_down_sync(0xffffffffu, mx1, 16));
        mx2 = fmaxf(mx2, __shfl_down_sync(0xffffffffu, mx2, 16));
        mx3 = fmaxf(mx3, __shfl_down_sync(0xffffffffu, mx3, 16));
        if (lane < 16) {
            smn[wrp][lane][0] = mn0; smn[wrp][lane][1] = mn1;
            smn[wrp][lane][2] = mn2; smn[wrp][lane][3] = mn3;
            smx[wrp][lane][0] = mx0; smx[wrp][lane][1] = mx1;
            smx[wrp][lane][2] = mx2; smx[wrp][lane][3] = mx3;
        }
        __syncthreads();
        if (tid < IN_DIM) {
            const int g = tid >> 2, q = tid & 3;
            float a =  INFINITY, c = -INFINITY;
            #pragma unroll
            for (int w = 0; w < 8; w++) {
                a = fminf(a, smn[w][g][q]);
                c = fmaxf(c, smx[w][g][q]);
            }
            g_pmin[b * IN_DIM + tid] = a;
            g_pmax[b * IN_DIM + tid] = c;
        }
    } else {
        // --- block 591: bins (thread 0) + M = embed @ W^T (all threads) ---
        if (tid == 0) {
            float l[NUM_BINS];
            float m = -INFINITY;
            #pragma unroll
            for (int i = 0; i < NUM_BINS; i++) { l[i] = logits[i]; m = fmaxf(m, l[i]); }
            float e[NUM_BINS], s = 0.f;
            #pragma unroll
            for (int i = 0; i < NUM_BINS; i++) {
                e[i] = (float)exp((double)(l[i] - m));  // correctly-rounded f32 exp
                s += e[i];
            }
            float cum = 0.f;
            #pragma unroll
            for (int i = 0; i < NUM_BINS; i++) {
                cum += __fdiv_rn(e[i], s);              // IEEE div under fast-math
                if (i < NTHRESH) g_bins[i] = cum;
            }
        }
        for (int i = tid; i < NUM_BINS * EMBED_DIM; i += TPB) {
            const int k = i >> 6, f = i & 63;
            const float* er = embed + k * EMBED_DIM;
            const float* wr = W + f * EMBED_DIM;
            float s = 0.f;
            #pragma unroll 8
            for (int e2 = 0; e2 < EMBED_DIM; e2++) s = fmaf(er[e2], wr[e2], s);
            g_M[i] = s;
        }
    }

    // ================= GRID BARRIER =================
    __threadfence();
    __syncthreads();
    if (tid == 0) s_ticket = atomicAdd(&g_count, 1);
    __syncthreads();

    if (s_ticket == GRID - 1) {
        // last-arriving block: finalize min/max
        __threadfence();  // acquire partials
        const int col = tid & 63, sub = tid >> 6;
        float mn =  INFINITY, mx = -INFINITY;
        #pragma unroll 4
        for (int i = sub; i < MMB; i += 4) {
            mn = fminf(mn, g_pmin[i * IN_DIM + col]);
            mx = fmaxf(mx, g_pmax[i * IN_DIM + col]);
        }
        rmn[sub][col] = mn;
        rmx[sub][col] = mx;
        __syncthreads();
        if (tid < IN_DIM) {
            float a = fminf(fminf(rmn[0][tid], rmn[1][tid]), fminf(rmn[2][tid], rmn[3][tid]));
            float c = fmaxf(fmaxf(rmx[0][tid], rmx[1][tid]), fmaxf(rmx[2][tid], rmx[3][tid]));
            g_mn[tid] = a;
            g_dn[tid] = (c - a) + 1e-6f;
        }
        if (tid == 0) g_count = 0;   // reset for next graph replay
        __threadfence();
        __syncthreads();
        if (tid == 0) atomicAdd(&g_release, 1u);
    }

    if (tid == 0) {
        while (*(volatile unsigned*)&g_release == s_snap) { __nanosleep(64); }
    }
    __syncthreads();
    __threadfence();

    // ================= PHASE 2 =================
    // out[b,f] = 64*(M[0][f]+bias[f]) + sum_{k=1..9} c_k * (M[k][f]-M[k-1][f])
    const int c0 = lane * 2;
    const int c1 = c0 + 1;
    const int w  = b * 8 + wrp;    // 0..4735

    const float mn0 = g_mn[c0], mn1 = g_mn[c1];
    const float dn0 = g_dn[c0], dn1 = g_dn[c1];

    float bins[NTHRESH];
    #pragma unroll
    for (int k = 0; k < NTHRESH; k++) bins[k] = g_bins[k];

    const float base0 = 64.f * (g_M[c0] + bias[c0]);
    const float base1 = 64.f * (g_M[c1] + bias[c1]);

    float D0[NTHRESH], D1[NTHRESH];
    #pragma unroll
    for (int k = 0; k < NTHRESH; k++) {
        D0[k] = g_M[(k + 1) * EMBED_DIM + c0] - g_M[k * EMBED_DIM + c0];
        D1[k] = g_M[(k + 1) * EMBED_DIM + c1] - g_M[k * EMBED_DIM + c1];
    }

    const float2* __restrict__ x2   = (const float2*)x;
    float2* __restrict__       out2 = (float2*)out;

    int row = w;
    // 2-row unrolled main loop (both loads issued before compute)
    while (row + NWARP < BATCH) {
        const float2 xa = x2[row * 32 + lane];
        const float2 xb = x2[(row + NWARP) * 32 + lane];

        const float a_xn0 = __fdiv_rn(xa.x - mn0, dn0);
        const float a_xn1 = __fdiv_rn(xa.y - mn1, dn1);
        const float b_xn0 = __fdiv_rn(xb.x - mn0, dn0);
        const float b_xn1 = __fdiv_rn(xb.y - mn1, dn1);

        float a0 = base0, a1 = base1, b0 = base0, b1 = base1;
        #pragma unroll
        for (int k = 0; k < NTHRESH; k++) {
            unsigned am0 = __ballot_sync(0xffffffffu, a_xn0 > bins[k]);
            unsigned am1 = __ballot_sync(0xffffffffu, a_xn1 > bins[k]);
            unsigned bm0 = __ballot_sync(0xffffffffu, b_xn0 > bins[k]);
            unsigned bm1 = __ballot_sync(0xffffffffu, b_xn1 > bins[k]);
            float fa = (float)(__popc(am0) + __popc(am1));
            float fb = (float)(__popc(bm0) + __popc(bm1));
            a0 = fmaf(fa, D0[k], a0);
            a1 = fmaf(fa, D1[k], a1);
            b0 = fmaf(fb, D0[k], b0);
            b1 = fmaf(fb, D1[k], b1);
        }
        out2[row * 32 + lane]           = make_float2(a0, a1);
        out2[(row + NWARP) * 32 + lane] = make_float2(b0, b1);
        row += 2 * NWARP;
    }
    if (row < BATCH) {
        const float2 xa = x2[row * 32 + lane];
        const float a_xn0 = __fdiv_rn(xa.x - mn0, dn0);
        const float a_xn1 = __fdiv_rn(xa.y - mn1, dn1);
        float a0 = base0, a1 = base1;
        #pragma unroll
        for (int k = 0; k < NTHRESH; k++) {
            unsigned am0 = __ballot_sync(0xffffffffu, a_xn0 > bins[k]);
            unsigned am1 = __ballot_sync(0xffffffffu, a_xn1 > bins[k]);
            float fa = (float)(__popc(am0) + __popc(am1));
            a0 = fmaf(fa, D0[k], a0);
            a1 = fmaf(fa, D1[k], a1);
        }
        out2[row * 32 + lane] = make_float2(a0, a1);
    }
}

extern "C" void kernel_launch(void* const* d_in, const int* in_sizes, int n_in,
                              void* d_out, int out_size) {
    const float* x      = (const float*)d_in[0];
    const float* logits = (const float*)d_in[1];
    const float* embed  = (const float*)d_in[2];
    const float* W      = (const float*)d_in[3];
    const float* bias   = (const float*)d_in[4];
    float* out          = (float*)d_out;

    dybem_fused<<<GRID, TPB>>>(x, logits, embed, W, bias, out);
}

// round 4
// speedup vs baseline: 1.1865x; 1.1397x over previous
#include <cuda_runtime.h>
#include <math.h>

#define BATCH     32768
#define IN_DIM    64
#define NUM_BINS  10
#define EMBED_DIM 64
#define NTHRESH   9

#define GRID  296                 // 148 SMs * 2 blocks -> all co-resident at <=128 regs
#define TPB   256
#define MMB   (GRID - 1)          // blocks 0..294 do min/max; block 295 does bins+M
#define T1    (MMB * TPB)         // 75520 threads; %16==0 keeps col-group invariant
#define NV    (BATCH * 16)        // x as float4 count
#define NWARP (GRID * 8)          // 2368 phase-2 warps

// ---- scratch (device globals; no allocation allowed) ----
__device__ float g_pmin[MMB * IN_DIM];
__device__ float g_pmax[MMB * IN_DIM];
__device__ float g_mn[IN_DIM];
__device__ float g_dn[IN_DIM];
__device__ float g_bins[NTHRESH];
__device__ float g_M[NUM_BINS * EMBED_DIM];   // M[k][f] = embed[k] . W[f]
__device__ int       g_count;                 // arrival counter (reset each launch)
__device__ unsigned  g_release;               // epoch counter (monotonic across replays)

__global__ void __launch_bounds__(TPB, 2)     // <=128 regs: NO spills in phase 2
dybem_fused(const float*  __restrict__ x,
            const float*  __restrict__ logits,
            const float*  __restrict__ embed,
            const float*  __restrict__ W,
            const float*  __restrict__ bias,
            float*        __restrict__ out) {
    const int tid  = threadIdx.x;
    const int lane = tid & 31;
    const int wrp  = tid >> 5;
    const int b    = blockIdx.x;

    __shared__ unsigned s_snap;
    __shared__ int      s_ticket;
    __shared__ float smn[8][16][4];
    __shared__ float smx[8][16][4];
    __shared__ float rmn[4][IN_DIM];
    __shared__ float rmx[4][IN_DIM];

    // Epoch snapshot BEFORE any work.
    if (tid == 0) s_snap = *(volatile unsigned*)&g_release;
    __syncthreads();

    // ================= PHASE 1 =================
    if (b < MMB) {
        const float4* __restrict__ x4 = (const float4*)x;
        const int tg = b * TPB + tid;
        float mn0 =  INFINITY, mn1 =  INFINITY, mn2 =  INFINITY, mn3 =  INFINITY;
        float mx0 = -INFINITY, mx1 = -INFINITY, mx2 = -INFINITY, mx3 = -INFINITY;
        // T1 % 16 == 0 so (idx % 16) == (tid % 16) is loop-invariant
        #pragma unroll 4
        for (int idx = tg; idx < NV; idx += T1) {
            float4 v = x4[idx];
            mn0 = fminf(mn0, v.x); mx0 = fmaxf(mx0, v.x);
            mn1 = fminf(mn1, v.y); mx1 = fmaxf(mx1, v.y);
            mn2 = fminf(mn2, v.z); mx2 = fmaxf(mx2, v.z);
            mn3 = fminf(mn3, v.w); mx3 = fmaxf(mx3, v.w);
        }
        mn0 = fminf(mn0, __shfl_down_sync(0xffffffffu, mn0, 16));
        mn1 = fminf(mn1, __shfl_down_sync(0xffffffffu, mn1, 16));
        mn2 = fminf(mn2, __shfl_down_sync(0xffffffffu, mn2, 16));
        mn3 = fminf(mn3, __shfl_down_sync(0xffffffffu, mn3, 16));
        mx0 = fmaxf(mx0, __shfl_down_sync(0xffffffffu, mx0, 16));
        mx1 = fmaxf(mx1, __shfl_down_sync(0xffffffffu, mx1, 16));
        mx2 = fmaxf(mx2, __shfl_down_sync(0xffffffffu, mx2, 16));
        mx3 = fmaxf(mx3, __shfl_down_sync(0xffffffffu, mx3, 16));
        if (lane < 16) {
            smn[wrp][lane][0] = mn0; smn[wrp][lane][1] = mn1;
            smn[wrp][lane][2] = mn2; smn[wrp][lane][3] = mn3;
            smx[wrp][lane][0] = mx0; smx[wrp][lane][1] = mx1;
            smx[wrp][lane][2] = mx2; smx[wrp][lane][3] = mx3;
        }
        __syncthreads();
        if (tid < IN_DIM) {
            const int g = tid >> 2, q = tid & 3;
            float a =  INFINITY, c = -INFINITY;
            #pragma unroll
            for (int w = 0; w < 8; w++) {
                a = fminf(a, smn[w][g][q]);
                c = fmaxf(c, smx[w][g][q]);
            }
            g_pmin[b * IN_DIM + tid] = a;
            g_pmax[b * IN_DIM + tid] = c;
        }
    } else {
        // --- block MMB: bins (thread 0) + M = embed @ W^T ---
        if (tid == 0) {
            float l[NUM_BINS];
            float m = -INFINITY;
            #pragma unroll
            for (int i = 0; i < NUM_BINS; i++) { l[i] = logits[i]; m = fmaxf(m, l[i]); }
            float e[NUM_BINS], s = 0.f;
            #pragma unroll
            for (int i = 0; i < NUM_BINS; i++) {
                e[i] = (float)exp((double)(l[i] - m));  // correctly-rounded f32 exp
                s += e[i];
            }
            float cum = 0.f;
            #pragma unroll
            for (int i = 0; i < NUM_BINS; i++) {
                cum += __fdiv_rn(e[i], s);              // IEEE div under fast-math
                if (i < NTHRESH) g_bins[i] = cum;
            }
        }
        for (int i = tid; i < NUM_BINS * EMBED_DIM; i += TPB) {
            const int k = i >> 6, f = i & 63;
            const float* er = embed + k * EMBED_DIM;
            const float* wr = W + f * EMBED_DIM;
            float s = 0.f;
            #pragma unroll 8
            for (int e2 = 0; e2 < EMBED_DIM; e2++) s = fmaf(er[e2], wr[e2], s);
            g_M[i] = s;
        }
    }

    // ================= GRID BARRIER =================
    __threadfence();
    __syncthreads();
    if (tid == 0) s_ticket = atomicAdd(&g_count, 1);
    __syncthreads();

    if (s_ticket == GRID - 1) {
        __threadfence();  // acquire partials
        const int col = tid & 63, sub = tid >> 6;
        float mn =  INFINITY, mx = -INFINITY;
        #pragma unroll 5
        for (int i = sub; i < MMB; i += 4) {
            mn = fminf(mn, g_pmin[i * IN_DIM + col]);
            mx = fmaxf(mx, g_pmax[i * IN_DIM + col]);
        }
        rmn[sub][col] = mn;
        rmx[sub][col] = mx;
        __syncthreads();
        if (tid < IN_DIM) {
            float a = fminf(fminf(rmn[0][tid], rmn[1][tid]), fminf(rmn[2][tid], rmn[3][tid]));
            float c = fmaxf(fmaxf(rmx[0][tid], rmx[1][tid]), fmaxf(rmx[2][tid], rmx[3][tid]));
            g_mn[tid] = a;
            g_dn[tid] = (c - a) + 1e-6f;
        }
        if (tid == 0) g_count = 0;   // reset for next graph replay
        __threadfence();
        __syncthreads();
        if (tid == 0) atomicAdd(&g_release, 1u);
    }

    if (tid == 0) {
        while (*(volatile unsigned*)&g_release == s_snap) { __nanosleep(64); }
    }
    __syncthreads();
    __threadfence();

    // ================= PHASE 2 =================
    // out[b,f] = 64*(M[0][f]+bias[f]) + sum_{k=1..9} c_k * (M[k][f]-M[k-1][f])
    const int c0 = lane * 2;
    const int c1 = c0 + 1;
    const int w  = b * 8 + wrp;    // 0..NWARP-1

    const float mn0 = g_mn[c0], mn1 = g_mn[c1];
    const float dn0 = g_dn[c0], dn1 = g_dn[c1];

    float bins[NTHRESH];
    #pragma unroll
    for (int k = 0; k < NTHRESH; k++) bins[k] = g_bins[k];

    const float base0 = 64.f * (g_M[c0] + bias[c0]);
    const float base1 = 64.f * (g_M[c1] + bias[c1]);

    float D0[NTHRESH], D1[NTHRESH];
    #pragma unroll
    for (int k = 0; k < NTHRESH; k++) {
        D0[k] = g_M[(k + 1) * EMBED_DIM + c0] - g_M[k * EMBED_DIM + c0];
        D1[k] = g_M[(k + 1) * EMBED_DIM + c1] - g_M[k * EMBED_DIM + c1];
    }

    const float2* __restrict__ x2   = (const float2*)x;
    float2* __restrict__       out2 = (float2*)out;

    int row = w;
    while (row + NWARP < BATCH) {
        const float2 xa = x2[row * 32 + lane];
        const float2 xb = x2[(row + NWARP) * 32 + lane];

        const float a_xn0 = __fdiv_rn(xa.x - mn0, dn0);
        const float a_xn1 = __fdiv_rn(xa.y - mn1, dn1);
        const float b_xn0 = __fdiv_rn(xb.x - mn0, dn0);
        const float b_xn1 = __fdiv_rn(xb.y - mn1, dn1);

        float a0 = base0, a1 = base1, b0 = base0, b1 = base1;
        #pragma unroll
        for (int k = 0; k < NTHRESH; k++) {
            unsigned am0 = __ballot_sync(0xffffffffu, a_xn0 > bins[k]);
            unsigned am1 = __ballot_sync(0xffffffffu, a_xn1 > bins[k]);
            unsigned bm0 = __ballot_sync(0xffffffffu, b_xn0 > bins[k]);
            unsigned bm1 = __ballot_sync(0xffffffffu, b_xn1 > bins[k]);
            float fa = (float)(__popc(am0) + __popc(am1));
            float fb = (float)(__popc(bm0) + __popc(bm1));
            a0 = fmaf(fa, D0[k], a0);
            a1 = fmaf(fa, D1[k], a1);
            b0 = fmaf(fb, D0[k], b0);
            b1 = fmaf(fb, D1[k], b1);
        }
        out2[row * 32 + lane]           = make_float2(a0, a1);
        out2[(row + NWARP) * 32 + lane] = make_float2(b0, b1);
        row += 2 * NWARP;
    }
    if (row < BATCH) {
        const float2 xa = x2[row * 32 + lane];
        const float a_xn0 = __fdiv_rn(xa.x - mn0, dn0);
        const float a_xn1 = __fdiv_rn(xa.y - mn1, dn1);
        float a0 = base0, a1 = base1;
        #pragma unroll
        for (int k = 0; k < NTHRESH; k++) {
            unsigned am0 = __ballot_sync(0xffffffffu, a_xn0 > bins[k]);
            unsigned am1 = __ballot_sync(0xffffffffu, a_xn1 > bins[k]);
            float fa = (float)(__popc(am0) + __popc(am1));
            a0 = fmaf(fa, D0[k], a0);
            a1 = fmaf(fa, D1[k], a1);
        }
        out2[row * 32 + lane] = make_float2(a0, a1);
    }
}

extern "C" void kernel_launch(void* const* d_in, const int* in_sizes, int n_in,
                              void* d_out, int out_size) {
    const float* x      = (const float*)d_in[0];
    const float* logits = (const float*)d_in[1];
    const float* embed  = (const float*)d_in[2];
    const float* W      = (const float*)d_in[3];
    const float* bias   = (const float*)d_in[4];
    float* out          = (float*)d_out;

    dybem_fused<<<GRID, TPB>>>(x, logits, embed, W, bias, out);
}

// round 5
// speedup vs baseline: 1.3887x; 1.1704x over previous
#include <cuda_runtime.h>
#include <math.h>

#define BATCH     32768
#define IN_DIM    64
#define NUM_BINS  10
#define EMBED_DIM 64
#define NTHRESH   9

#define GRID   444                // 148 SMs * 3 blocks co-resident (<=83 regs)
#define TPB    256
#define MMB    (GRID - 1)         // blocks 0..442 min/max; block 443 bins+M
#define T1     (MMB * TPB)        // %16==0 -> float4 column-group invariant
#define NV     (BATCH * 16)
#define NWARP  (GRID * 8)         // 3552 phase-2 warps
#define NCHUNK (BATCH / 4)        // 8192 chunks of 4 rows

#define E8(x)  x,x,x,x,x,x,x,x
#define E64(x) E8(x),E8(x),E8(x),E8(x),E8(x),E8(x),E8(x),E8(x)

// monotone float<->uint encoding: unsigned order == float order (NaN-free data)
__device__ __forceinline__ unsigned fenc(float f) {
    unsigned u = __float_as_uint(f);
    return (u & 0x80000000u) ? ~u : (u | 0x80000000u);
}
__device__ __forceinline__ float fdec(unsigned e) {
    unsigned u = (e & 0x80000000u) ? (e ^ 0x80000000u) : ~e;
    return __uint_as_float(u);
}

// ---- scratch (device globals; no allocation allowed) ----
__device__ unsigned g_minenc[IN_DIM] = { E64(0xFF800000u) };  // enc(+INF)
__device__ unsigned g_maxenc[IN_DIM] = { E64(0x007FFFFFu) };  // enc(-INF)
__device__ float    g_mn[IN_DIM];
__device__ float    g_dn[IN_DIM];
__device__ float    g_bins[NTHRESH];
__device__ float    g_M[NUM_BINS * EMBED_DIM];
__device__ int      g_count;
__device__ unsigned g_release;

__global__ void __launch_bounds__(TPB, 3)
dybem_fused(const float*  __restrict__ x,
            const float*  __restrict__ logits,
            const float*  __restrict__ embed,
            const float*  __restrict__ W,
            const float*  __restrict__ bias,
            float*        __restrict__ out) {
    const int tid  = threadIdx.x;
    const int lane = tid & 31;
    const int wrp  = tid >> 5;
    const int b    = blockIdx.x;

    __shared__ unsigned s_snap;
    __shared__ int      s_ticket;
    __shared__ float smn[8][16][4];
    __shared__ float smx[8][16][4];

    if (tid == 0) s_snap = *(volatile unsigned*)&g_release;
    __syncthreads();

    // ================= PHASE 1 =================
    if (b < MMB) {
        const float4* __restrict__ x4 = (const float4*)x;
        const int tg = b * TPB + tid;
        float mn0 =  INFINITY, mn1 =  INFINITY, mn2 =  INFINITY, mn3 =  INFINITY;
        float mx0 = -INFINITY, mx1 = -INFINITY, mx2 = -INFINITY, mx3 = -INFINITY;
        #pragma unroll 5
        for (int idx = tg; idx < NV; idx += T1) {
            float4 v = x4[idx];
            mn0 = fminf(mn0, v.x); mx0 = fmaxf(mx0, v.x);
            mn1 = fminf(mn1, v.y); mx1 = fmaxf(mx1, v.y);
            mn2 = fminf(mn2, v.z); mx2 = fmaxf(mx2, v.z);
            mn3 = fminf(mn3, v.w); mx3 = fmaxf(mx3, v.w);
        }
        mn0 = fminf(mn0, __shfl_down_sync(0xffffffffu, mn0, 16));
        mn1 = fminf(mn1, __shfl_down_sync(0xffffffffu, mn1, 16));
        mn2 = fminf(mn2, __shfl_down_sync(0xffffffffu, mn2, 16));
        mn3 = fminf(mn3, __shfl_down_sync(0xffffffffu, mn3, 16));
        mx0 = fmaxf(mx0, __shfl_down_sync(0xffffffffu, mx0, 16));
        mx1 = fmaxf(mx1, __shfl_down_sync(0xffffffffu, mx1, 16));
        mx2 = fmaxf(mx2, __shfl_down_sync(0xffffffffu, mx2, 16));
        mx3 = fmaxf(mx3, __shfl_down_sync(0xffffffffu, mx3, 16));
        if (lane < 16) {
            smn[wrp][lane][0] = mn0; smn[wrp][lane][1] = mn1;
            smn[wrp][lane][2] = mn2; smn[wrp][lane][3] = mn3;
            smx[wrp][lane][0] = mx0; smx[wrp][lane][1] = mx1;
            smx[wrp][lane][2] = mx2; smx[wrp][lane][3] = mx3;
        }
        __syncthreads();
        if (tid < IN_DIM) {
            const int g = tid >> 2, q = tid & 3;
            float a =  INFINITY, c = -INFINITY;
            #pragma unroll
            for (int w = 0; w < 8; w++) {
                a = fminf(a, smn[w][g][q]);
                c = fmaxf(c, smx[w][g][q]);
            }
            atomicMin(&g_minenc[tid], fenc(a));
            atomicMax(&g_maxenc[tid], fenc(c));
        }
    } else {
        // --- block MMB: bins (thread 0) + M = embed @ W^T ---
        if (tid == 0) {
            float l[NUM_BINS];
            float m = -INFINITY;
            #pragma unroll
            for (int i = 0; i < NUM_BINS; i++) { l[i] = logits[i]; m = fmaxf(m, l[i]); }
            float e[NUM_BINS], s = 0.f;
            #pragma unroll
            for (int i = 0; i < NUM_BINS; i++) {
                e[i] = (float)exp((double)(l[i] - m));  // correctly-rounded f32 exp
                s += e[i];
            }
            float cum = 0.f;
            #pragma unroll
            for (int i = 0; i < NUM_BINS; i++) {
                cum += __fdiv_rn(e[i], s);              // IEEE div under fast-math
                if (i < NTHRESH) g_bins[i] = cum;
            }
        }
        for (int i = tid; i < NUM_BINS * EMBED_DIM; i += TPB) {
            const int k = i >> 6, f = i & 63;
            const float* er = embed + k * EMBED_DIM;
            const float* wr = W + f * EMBED_DIM;
            float s = 0.f;
            #pragma unroll 8
            for (int e2 = 0; e2 < EMBED_DIM; e2++) s = fmaf(er[e2], wr[e2], s);
            g_M[i] = s;
        }
    }

    // ================= GRID BARRIER =================
    __threadfence();
    __syncthreads();
    if (tid == 0) s_ticket = atomicAdd(&g_count, 1);
    __syncthreads();

    if (s_ticket == GRID - 1) {
        __threadfence();  // acquire all atomics
        if (tid < IN_DIM) {
            unsigned emin = *(volatile unsigned*)&g_minenc[tid];
            unsigned emax = *(volatile unsigned*)&g_maxenc[tid];
            float a = fdec(emin), c = fdec(emax);
            g_mn[tid] = a;
            g_dn[tid] = (c - a) + 1e-6f;
            g_minenc[tid] = 0xFF800000u;   // reset for next graph replay
            g_maxenc[tid] = 0x007FFFFFu;
        }
        if (tid == 0) g_count = 0;
        __threadfence();
        __syncthreads();
        if (tid == 0) atomicAdd(&g_release, 1u);
    }

    if (tid == 0) {
        while (*(volatile unsigned*)&g_release == s_snap) { __nanosleep(32); }
    }
    __syncthreads();
    __threadfence();

    // ================= PHASE 2 =================
    // out[b,f] = 64*(M[0][f]+bias[f]) + sum_{k=1..9} c_k * (M[k][f]-M[k-1][f])
    // c_k per row via packed-byte counts + 3x REDUX.ADD. 4 rows/warp-iter.
    const int c0 = lane * 2;
    const int c1 = c0 + 1;
    const int w  = b * 8 + wrp;

    const float mn0 = g_mn[c0], mn1 = g_mn[c1];
    const float dn0 = g_dn[c0], dn1 = g_dn[c1];

    float bins[NTHRESH];
    #pragma unroll
    for (int k = 0; k < NTHRESH; k++) bins[k] = g_bins[k];

    const float base0 = 64.f * (g_M[c0] + bias[c0]);
    const float base1 = 64.f * (g_M[c1] + bias[c1]);

    float D0[NTHRESH], D1[NTHRESH];
    #pragma unroll
    for (int k = 0; k < NTHRESH; k++) {
        D0[k] = g_M[(k + 1) * EMBED_DIM + c0] - g_M[k * EMBED_DIM + c0];
        D1[k] = g_M[(k + 1) * EMBED_DIM + c1] - g_M[k * EMBED_DIM + c1];
    }

    const float2* __restrict__ x2   = (const float2*)x;
    float2* __restrict__       out2 = (float2*)out;

    for (int c = w; c < NCHUNK; c += NWARP) {
        const float2* xp = x2 + c * 128 + lane;   // 4 consecutive rows
        float2 v0 = xp[0];
        float2 v1 = xp[32];
        float2 v2 = xp[64];
        float2 v3 = xp[96];

        // exact reference f32 sequence: sub then IEEE divide
        float xa0 = __fdiv_rn(v0.x - mn0, dn0), xa1 = __fdiv_rn(v0.y - mn1, dn1);
        float xb0 = __fdiv_rn(v1.x - mn0, dn0), xb1 = __fdiv_rn(v1.y - mn1, dn1);
        float xc0 = __fdiv_rn(v2.x - mn0, dn0), xc1 = __fdiv_rn(v2.y - mn1, dn1);
        float xd0 = __fdiv_rn(v3.x - mn0, dn0), xd1 = __fdiv_rn(v3.y - mn1, dn1);

        // packed byte-counters: word0 = k0..3, word1 = k4..7, word2 = k8
        unsigned qa0 = 0, qa1 = 0, qa2 = 0;
        unsigned qb0 = 0, qb1 = 0, qb2 = 0;
        unsigned qc0 = 0, qc1 = 0, qc2 = 0;
        unsigned qd0 = 0, qd1 = 0, qd2 = 0;
        #pragma unroll
        for (int k = 0; k < 4; k++) {
            const unsigned wgt = 1u << (8 * k);
            qa0 += (xa0 > bins[k]) ? wgt : 0u;  qa0 += (xa1 > bins[k]) ? wgt : 0u;
            qb0 += (xb0 > bins[k]) ? wgt : 0u;  qb0 += (xb1 > bins[k]) ? wgt : 0u;
            qc0 += (xc0 > bins[k]) ? wgt : 0u;  qc0 += (xc1 > bins[k]) ? wgt : 0u;
            qd0 += (xd0 > bins[k]) ? wgt : 0u;  qd0 += (xd1 > bins[k]) ? wgt : 0u;
        }
        #pragma unroll
        for (int k = 4; k < 8; k++) {
            const unsigned wgt = 1u << (8 * (k - 4));
            qa1 += (xa0 > bins[k]) ? wgt : 0u;  qa1 += (xa1 > bins[k]) ? wgt : 0u;
            qb1 += (xb0 > bins[k]) ? wgt : 0u;  qb1 += (xb1 > bins[k]) ? wgt : 0u;
            qc1 += (xc0 > bins[k]) ? wgt : 0u;  qc1 += (xc1 > bins[k]) ? wgt : 0u;
            qd1 += (xd0 > bins[k]) ? wgt : 0u;  qd1 += (xd1 > bins[k]) ? wgt : 0u;
        }
        qa2 += (xa0 > bins[8]) ? 1u : 0u;  qa2 += (xa1 > bins[8]) ? 1u : 0u;
        qb2 += (xb0 > bins[8]) ? 1u : 0u;  qb2 += (xb1 > bins[8]) ? 1u : 0u;
        qc2 += (xc0 > bins[8]) ? 1u : 0u;  qc2 += (xc1 > bins[8]) ? 1u : 0u;
        qd2 += (xd0 > bins[8]) ? 1u : 0u;  qd2 += (xd1 > bins[8]) ? 1u : 0u;

        // warp-wide byte-wise sums (counts <= 64 per byte, no carry)
        qa0 = __reduce_add_sync(0xffffffffu, qa0);
        qa1 = __reduce_add_sync(0xffffffffu, qa1);
        qa2 = __reduce_add_sync(0xffffffffu, qa2);
        qb0 = __reduce_add_sync(0xffffffffu, qb0);
        qb1 = __reduce_add_sync(0xffffffffu, qb1);
        qb2 = __reduce_add_sync(0xffffffffu, qb2);
        qc0 = __reduce_add_sync(0xffffffffu, qc0);
        qc1 = __reduce_add_sync(0xffffffffu, qc1);
        qc2 = __reduce_add_sync(0xffffffffu, qc2);
        qd0 = __reduce_add_sync(0xffffffffu, qd0);
        qd1 = __reduce_add_sync(0xffffffffu, qd1);
        qd2 = __reduce_add_sync(0xffffffffu, qd2);

        float a0 = base0, a1 = base1, b0 = base0, b1 = base1;
        float cc0 = base0, cc1 = base1, d0 = base0, d1 = base1;
        #pragma unroll
        for (int k = 0; k < 9; k++) {
            unsigned ca = (k < 4) ? (qa0 >> (8 * k)) : ((k < 8) ? (qa1 >> (8 * (k - 4))) : qa2);
            unsigned cb = (k < 4) ? (qb0 >> (8 * k)) : ((k < 8) ? (qb1 >> (8 * (k - 4))) : qb2);
            unsigned cg = (k < 4) ? (qc0 >> (8 * k)) : ((k < 8) ? (qc1 >> (8 * (k - 4))) : qc2);
            unsigned cd = (k < 4) ? (qd0 >> (8 * k)) : ((k < 8) ? (qd1 >> (8 * (k - 4))) : qd2);
            float fa = (float)(ca & 0xffu);
            float fb = (float)(cb & 0xffu);
            float fc = (float)(cg & 0xffu);
            float fd = (float)(cd & 0xffu);
            a0  = fmaf(fa, D0[k], a0);   a1  = fmaf(fa, D1[k], a1);
            b0  = fmaf(fb, D0[k], b0);   b1  = fmaf(fb, D1[k], b1);
            cc0 = fmaf(fc, D0[k], cc0);  cc1 = fmaf(fc, D1[k], cc1);
            d0  = fmaf(fd, D0[k], d0);   d1  = fmaf(fd, D1[k], d1);
        }
        float2* op = out2 + c * 128 + lane;
        op[0]  = make_float2(a0, a1);
        op[32] = make_float2(b0, b1);
        op[64] = make_float2(cc0, cc1);
        op[96] = make_float2(d0, d1);
    }
}

extern "C" void kernel_launch(void* const* d_in, const int* in_sizes, int n_in,
                              void* d_out, int out_size) {
    const float* x      = (const float*)d_in[0];
    const float* logits = (const float*)d_in[1];
    const float* embed  = (const float*)d_in[2];
    const float* W      = (const float*)d_in[3];
    const float* bias   = (const float*)d_in[4];
    float* out          = (float*)d_out;

    dybem_fused<<<GRID, TPB>>>(x, logits, embed, W, bias, out);
}

// round 6
// speedup vs baseline: 2.2813x; 1.6428x over previous
#include <cuda_runtime.h>
#include <math.h>

#define BATCH     32768
#define IN_DIM    64
#define NUM_BINS  10
#define EMBED_DIM 64
#define NTHRESH   9

#define GRID   444                // 148 SMs * 3 blocks co-resident (<=83 regs)
#define TPB    256
#define MMB    (GRID - 1)         // blocks 0..442 min/max; block 443 bins+M
#define T1     (MMB * TPB)        // %16==0 -> float4 column-group invariant
#define NV     (BATCH * 16)
#define NWARP  (GRID * 8)         // 3552 phase-2 warps
#define NCHUNK (BATCH / 4)        // 8192 chunks of 4 rows

#define E8(x)  x,x,x,x,x,x,x,x
#define E64(x) E8(x),E8(x),E8(x),E8(x),E8(x),E8(x),E8(x),E8(x)

// monotone float<->uint encoding: unsigned order == float order (NaN-free data)
__device__ __forceinline__ unsigned fenc(float f) {
    unsigned u = __float_as_uint(f);
    return (u & 0x80000000u) ? ~u : (u | 0x80000000u);
}
__device__ __forceinline__ float fdec(unsigned e) {
    unsigned u = (e & 0x80000000u) ? (e ^ 0x80000000u) : ~e;
    return __uint_as_float(u);
}

// ---- scratch (device globals; no allocation allowed) ----
__device__ unsigned g_minenc[IN_DIM] = { E64(0xFF800000u) };  // enc(+INF)
__device__ unsigned g_maxenc[IN_DIM] = { E64(0x007FFFFFu) };  // enc(-INF)
__device__ float    g_mn[IN_DIM];
__device__ float    g_dn[IN_DIM];
__device__ float    g_bins[NTHRESH];
__device__ float    g_M[NUM_BINS * EMBED_DIM];
__device__ int      g_count;
__device__ unsigned g_release;

__global__ void __launch_bounds__(TPB, 3)
dybem_fused(const float*  __restrict__ x,
            const float*  __restrict__ logits,
            const float*  __restrict__ embed,
            const float*  __restrict__ W,
            const float*  __restrict__ bias,
            float*        __restrict__ out) {
    const int tid  = threadIdx.x;
    const int lane = tid & 31;
    const int wrp  = tid >> 5;
    const int b    = blockIdx.x;

    __shared__ unsigned s_snap;
    __shared__ int      s_ticket;
    // union-style: min/max blocks use smm; bins+M block uses sWt/sEm
    __shared__ float smm[2][8][16][4];
    __shared__ float sWt[EMBED_DIM * 65];          // Wt[e][f] padded (conflict-free)
    __shared__ float sEm[NUM_BINS * EMBED_DIM];

    if (tid == 0) s_snap = *(volatile unsigned*)&g_release;
    __syncthreads();

    // ================= PHASE 1 =================
    if (b < MMB) {
        const float4* __restrict__ x4 = (const float4*)x;
        const int tg = b * TPB + tid;
        float mn0 =  INFINITY, mn1 =  INFINITY, mn2 =  INFINITY, mn3 =  INFINITY;
        float mx0 = -INFINITY, mx1 = -INFINITY, mx2 = -INFINITY, mx3 = -INFINITY;
        #pragma unroll 5
        for (int idx = tg; idx < NV; idx += T1) {
            float4 v = x4[idx];
            mn0 = fminf(mn0, v.x); mx0 = fmaxf(mx0, v.x);
            mn1 = fminf(mn1, v.y); mx1 = fmaxf(mx1, v.y);
            mn2 = fminf(mn2, v.z); mx2 = fmaxf(mx2, v.z);
            mn3 = fminf(mn3, v.w); mx3 = fmaxf(mx3, v.w);
        }
        mn0 = fminf(mn0, __shfl_down_sync(0xffffffffu, mn0, 16));
        mn1 = fminf(mn1, __shfl_down_sync(0xffffffffu, mn1, 16));
        mn2 = fminf(mn2, __shfl_down_sync(0xffffffffu, mn2, 16));
        mn3 = fminf(mn3, __shfl_down_sync(0xffffffffu, mn3, 16));
        mx0 = fmaxf(mx0, __shfl_down_sync(0xffffffffu, mx0, 16));
        mx1 = fmaxf(mx1, __shfl_down_sync(0xffffffffu, mx1, 16));
        mx2 = fmaxf(mx2, __shfl_down_sync(0xffffffffu, mx2, 16));
        mx3 = fmaxf(mx3, __shfl_down_sync(0xffffffffu, mx3, 16));
        if (lane < 16) {
            smm[0][wrp][lane][0] = mn0; smm[0][wrp][lane][1] = mn1;
            smm[0][wrp][lane][2] = mn2; smm[0][wrp][lane][3] = mn3;
            smm[1][wrp][lane][0] = mx0; smm[1][wrp][lane][1] = mx1;
            smm[1][wrp][lane][2] = mx2; smm[1][wrp][lane][3] = mx3;
        }
        __syncthreads();
        if (tid < IN_DIM) {
            const int g = tid >> 2, q = tid & 3;
            float a =  INFINITY, c = -INFINITY;
            #pragma unroll
            for (int w = 0; w < 8; w++) {
                a = fminf(a, smm[0][w][g][q]);
                c = fmaxf(c, smm[1][w][g][q]);
            }
            atomicMin(&g_minenc[tid], fenc(a));
            atomicMax(&g_maxenc[tid], fenc(c));
        }
    } else {
        // --- block MMB: bins (thread 0) + M = embed @ W^T via smem staging ---
        // Stage W coalesced, store TRANSPOSED into padded smem: Wt[e][f]=W[f][e]
        #pragma unroll
        for (int i = tid; i < EMBED_DIM * EMBED_DIM; i += TPB) {
            const int f = i >> 6, e = i & 63;
            sWt[e * 65 + f] = W[i];           // read coalesced, write conflict-free
        }
        for (int i = tid; i < NUM_BINS * EMBED_DIM; i += TPB)
            sEm[i] = embed[i];
        if (tid == 0) {
            float l[NUM_BINS];
            float m = -INFINITY;
            #pragma unroll
            for (int i = 0; i < NUM_BINS; i++) { l[i] = logits[i]; m = fmaxf(m, l[i]); }
            float e[NUM_BINS], s = 0.f;
            #pragma unroll
            for (int i = 0; i < NUM_BINS; i++) {
                e[i] = (float)exp((double)(l[i] - m));  // correctly-rounded f32 exp
                s += e[i];
            }
            float cum = 0.f;
            #pragma unroll
            for (int i = 0; i < NUM_BINS; i++) {
                cum += __fdiv_rn(e[i], s);              // IEEE div under fast-math
                if (i < NTHRESH) g_bins[i] = cum;
            }
        }
        __syncthreads();
        // M[k][f] = sum_e em[k][e] * Wt[e][f]: lane f consecutive -> no conflicts
        for (int i = tid; i < NUM_BINS * EMBED_DIM; i += TPB) {
            const int k = i >> 6, f = i & 63;
            const float* em = sEm + k * EMBED_DIM;
            float s = 0.f;
            #pragma unroll 16
            for (int e2 = 0; e2 < EMBED_DIM; e2++)
                s = fmaf(em[e2], sWt[e2 * 65 + f], s);
            g_M[i] = s;
        }
    }

    // ================= GRID BARRIER =================
    __threadfence();
    __syncthreads();
    if (tid == 0) s_ticket = atomicAdd(&g_count, 1);
    __syncthreads();

    if (s_ticket == GRID - 1) {
        __threadfence();  // acquire all atomics
        if (tid < IN_DIM) {
            unsigned emin = *(volatile unsigned*)&g_minenc[tid];
            unsigned emax = *(volatile unsigned*)&g_maxenc[tid];
            float a = fdec(emin), c = fdec(emax);
            g_mn[tid] = a;
            g_dn[tid] = (c - a) + 1e-6f;
            g_minenc[tid] = 0xFF800000u;   // reset for next graph replay
            g_maxenc[tid] = 0x007FFFFFu;
        }
        if (tid == 0) g_count = 0;
        __threadfence();
        __syncthreads();
        if (tid == 0) atomicAdd(&g_release, 1u);
    }

    if (tid == 0) {
        while (*(volatile unsigned*)&g_release == s_snap) { __nanosleep(32); }
    }
    __syncthreads();
    __threadfence();

    // ================= PHASE 2 =================
    // out[b,f] = 64*(M[0][f]+bias[f]) + sum_{k=1..9} c_k * (M[k][f]-M[k-1][f])
    // c_k per row via packed-byte counts + 3x REDUX.ADD. 4 rows/warp-iter.
    const int c0 = lane * 2;
    const int c1 = c0 + 1;
    const int w  = b * 8 + wrp;

    const float mn0 = g_mn[c0], mn1 = g_mn[c1];
    const float dn0 = g_dn[c0], dn1 = g_dn[c1];

    float bins[NTHRESH];
    #pragma unroll
    for (int k = 0; k < NTHRESH; k++) bins[k] = g_bins[k];

    const float base0 = 64.f * (g_M[c0] + bias[c0]);
    const float base1 = 64.f * (g_M[c1] + bias[c1]);

    float D0[NTHRESH], D1[NTHRESH];
    #pragma unroll
    for (int k = 0; k < NTHRESH; k++) {
        D0[k] = g_M[(k + 1) * EMBED_DIM + c0] - g_M[k * EMBED_DIM + c0];
        D1[k] = g_M[(k + 1) * EMBED_DIM + c1] - g_M[k * EMBED_DIM + c1];
    }

    const float2* __restrict__ x2   = (const float2*)x;
    float2* __restrict__       out2 = (float2*)out;

    for (int c = w; c < NCHUNK; c += NWARP) {
        const float2* xp = x2 + c * 128 + lane;   // 4 consecutive rows
        float2 v0 = xp[0];
        float2 v1 = xp[32];
        float2 v2 = xp[64];
        float2 v3 = xp[96];

        // exact reference f32 sequence: sub then IEEE divide
        float xa0 = __fdiv_rn(v0.x - mn0, dn0), xa1 = __fdiv_rn(v0.y - mn1, dn1);
        float xb0 = __fdiv_rn(v1.x - mn0, dn0), xb1 = __fdiv_rn(v1.y - mn1, dn1);
        float xc0 = __fdiv_rn(v2.x - mn0, dn0), xc1 = __fdiv_rn(v2.y - mn1, dn1);
        float xd0 = __fdiv_rn(v3.x - mn0, dn0), xd1 = __fdiv_rn(v3.y - mn1, dn1);

        // packed byte-counters: word0 = k0..3, word1 = k4..7, word2 = k8
        unsigned qa0 = 0, qa1 = 0, qa2 = 0;
        unsigned qb0 = 0, qb1 = 0, qb2 = 0;
        unsigned qc0 = 0, qc1 = 0, qc2 = 0;
        unsigned qd0 = 0, qd1 = 0, qd2 = 0;
        #pragma unroll
        for (int k = 0; k < 4; k++) {
            const unsigned wgt = 1u << (8 * k);
            qa0 += (xa0 > bins[k]) ? wgt : 0u;  qa0 += (xa1 > bins[k]) ? wgt : 0u;
            qb0 += (xb0 > bins[k]) ? wgt : 0u;  qb0 += (xb1 > bins[k]) ? wgt : 0u;
            qc0 += (xc0 > bins[k]) ? wgt : 0u;  qc0 += (xc1 > bins[k]) ? wgt : 0u;
            qd0 += (xd0 > bins[k]) ? wgt : 0u;  qd0 += (xd1 > bins[k]) ? wgt : 0u;
        }
        #pragma unroll
        for (int k = 4; k < 8; k++) {
            const unsigned wgt = 1u << (8 * (k - 4));
            qa1 += (xa0 > bins[k]) ? wgt : 0u;  qa1 += (xa1 > bins[k]) ? wgt : 0u;
            qb1 += (xb0 > bins[k]) ? wgt : 0u;  qb1 += (xb1 > bins[k]) ? wgt : 0u;
            qc1 += (xc0 > bins[k]) ? wgt : 0u;  qc1 += (xc1 > bins[k]) ? wgt : 0u;
            qd1 += (xd0 > bins[k]) ? wgt : 0u;  qd1 += (xd1 > bins[k]) ? wgt : 0u;
        }
        qa2 += (xa0 > bins[8]) ? 1u : 0u;  qa2 += (xa1 > bins[8]) ? 1u : 0u;
        qb2 += (xb0 > bins[8]) ? 1u : 0u;  qb2 += (xb1 > bins[8]) ? 1u : 0u;
        qc2 += (xc0 > bins[8]) ? 1u : 0u;  qc2 += (xc1 > bins[8]) ? 1u : 0u;
        qd2 += (xd0 > bins[8]) ? 1u : 0u;  qd2 += (xd1 > bins[8]) ? 1u : 0u;

        // warp-wide byte-wise sums (counts <= 64 per byte, no carry)
        qa0 = __reduce_add_sync(0xffffffffu, qa0);
        qa1 = __reduce_add_sync(0xffffffffu, qa1);
        qa2 = __reduce_add_sync(0xffffffffu, qa2);
        qb0 = __reduce_add_sync(0xffffffffu, qb0);
        qb1 = __reduce_add_sync(0xffffffffu, qb1);
        qb2 = __reduce_add_sync(0xffffffffu, qb2);
        qc0 = __reduce_add_sync(0xffffffffu, qc0);
        qc1 = __reduce_add_sync(0xffffffffu, qc1);
        qc2 = __reduce_add_sync(0xffffffffu, qc2);
        qd0 = __reduce_add_sync(0xffffffffu, qd0);
        qd1 = __reduce_add_sync(0xffffffffu, qd1);
        qd2 = __reduce_add_sync(0xffffffffu, qd2);

        float a0 = base0, a1 = base1, b0 = base0, b1 = base1;
        float cc0 = base0, cc1 = base1, d0 = base0, d1 = base1;
        #pragma unroll
        for (int k = 0; k < 9; k++) {
            unsigned ca = (k < 4) ? (qa0 >> (8 * k)) : ((k < 8) ? (qa1 >> (8 * (k - 4))) : qa2);
            unsigned cb = (k < 4) ? (qb0 >> (8 * k)) : ((k < 8) ? (qb1 >> (8 * (k - 4))) : qb2);
            unsigned cg = (k < 4) ? (qc0 >> (8 * k)) : ((k < 8) ? (qc1 >> (8 * (k - 4))) : qc2);
            unsigned cd = (k < 4) ? (qd0 >> (8 * k)) : ((k < 8) ? (qd1 >> (8 * (k - 4))) : qd2);
            float fa = (float)(ca & 0xffu);
            float fb = (float)(cb & 0xffu);
            float fc = (float)(cg & 0xffu);
            float fd = (float)(cd & 0xffu);
            a0  = fmaf(fa, D0[k], a0);   a1  = fmaf(fa, D1[k], a1);
            b0  = fmaf(fb, D0[k], b0);   b1  = fmaf(fb, D1[k], b1);
            cc0 = fmaf(fc, D0[k], cc0);  cc1 = fmaf(fc, D1[k], cc1);
            d0  = fmaf(fd, D0[k], d0);   d1  = fmaf(fd, D1[k], d1);
        }
        float2* op = out2 + c * 128 + lane;
        op[0]  = make_float2(a0, a1);
        op[32] = make_float2(b0, b1);
        op[64] = make_float2(cc0, cc1);
        op[96] = make_float2(d0, d1);
    }
}

extern "C" void kernel_launch(void* const* d_in, const int* in_sizes, int n_in,
                              void* d_out, int out_size) {
    const float* x      = (const float*)d_in[0];
    const float* logits = (const float*)d_in[1];
    const float* embed  = (const float*)d_in[2];
    const float* W      = (const float*)d_in[3];
    const float* bias   = (const float*)d_in[4];
    float* out          = (float*)d_out;

    dybem_fused<<<GRID, TPB>>>(x, logits, embed, W, bias, out);
}

// round 7
// speedup vs baseline: 2.8062x; 1.2301x over previous
#include <cuda_runtime.h>
#include <math.h>

#define BATCH     32768
#define IN_DIM    64
#define NUM_BINS  10
#define EMBED_DIM 64
#define NTHRESH   9

#define GRID   444                // 148 SMs * 3 blocks co-resident (<=83 regs)
#define TPB    256
#define MMB    (GRID - 1)         // blocks 0..442 min/max; block 443 bins+M
#define T1     (MMB * TPB)        // %16==0 -> float4 column-group invariant
#define NV     (BATCH * 16)
#define NWARP  (GRID * 8)         // 3552 phase-2 warps

#define E8(x)  x,x,x,x,x,x,x,x
#define E64(x) E8(x),E8(x),E8(x),E8(x),E8(x),E8(x),E8(x),E8(x)

// monotone float<->uint encoding: unsigned order == float order (NaN-free data)
__device__ __forceinline__ unsigned fenc(float f) {
    unsigned u = __float_as_uint(f);
    return (u & 0x80000000u) ? ~u : (u | 0x80000000u);
}
__device__ __forceinline__ float fdec(unsigned e) {
    unsigned u = (e & 0x80000000u) ? (e ^ 0x80000000u) : ~e;
    return __uint_as_float(u);
}

// ---- scratch (device globals; no allocation allowed) ----
__device__ unsigned g_minenc[IN_DIM] = { E64(0xFF800000u) };  // enc(+INF)
__device__ unsigned g_maxenc[IN_DIM] = { E64(0x007FFFFFu) };  // enc(-INF)
__device__ float    g_mn[IN_DIM];
__device__ float    g_dn[IN_DIM];
__device__ float    g_bins[NTHRESH];
__device__ float    g_M[NUM_BINS * EMBED_DIM];
__device__ int      g_count;
__device__ unsigned g_release;

__global__ void __launch_bounds__(TPB, 3)
dybem_fused(const float*  __restrict__ x,
            const float*  __restrict__ logits,
            const float*  __restrict__ embed,
            const float*  __restrict__ W,
            const float*  __restrict__ bias,
            float*        __restrict__ out) {
    const int tid  = threadIdx.x;
    const int lane = tid & 31;
    const int wrp  = tid >> 5;
    const int b    = blockIdx.x;

    __shared__ unsigned s_snap;
    __shared__ int      s_ticket;
    // union-style: min/max blocks use smm; bins+M block uses sWt/sEm/sE
    __shared__ float smm[2][8][16][4];
    __shared__ float sWt[EMBED_DIM * 65];          // Wt[e][f] padded (conflict-free)
    __shared__ float sEm[NUM_BINS * EMBED_DIM];
    __shared__ float sE[NUM_BINS];                 // parallel exp results

    if (tid == 0) s_snap = *(volatile unsigned*)&g_release;
    __syncthreads();

    // ================= PHASE 1 =================
    if (b < MMB) {
        const float4* __restrict__ x4 = (const float4*)x;
        const int tg = b * TPB + tid;
        float mn0 =  INFINITY, mn1 =  INFINITY, mn2 =  INFINITY, mn3 =  INFINITY;
        float mx0 = -INFINITY, mx1 = -INFINITY, mx2 = -INFINITY, mx3 = -INFINITY;
        #pragma unroll 5
        for (int idx = tg; idx < NV; idx += T1) {
            float4 v = x4[idx];
            mn0 = fminf(mn0, v.x); mx0 = fmaxf(mx0, v.x);
            mn1 = fminf(mn1, v.y); mx1 = fmaxf(mx1, v.y);
            mn2 = fminf(mn2, v.z); mx2 = fmaxf(mx2, v.z);
            mn3 = fminf(mn3, v.w); mx3 = fmaxf(mx3, v.w);
        }
        mn0 = fminf(mn0, __shfl_down_sync(0xffffffffu, mn0, 16));
        mn1 = fminf(mn1, __shfl_down_sync(0xffffffffu, mn1, 16));
        mn2 = fminf(mn2, __shfl_down_sync(0xffffffffu, mn2, 16));
        mn3 = fminf(mn3, __shfl_down_sync(0xffffffffu, mn3, 16));
        mx0 = fmaxf(mx0, __shfl_down_sync(0xffffffffu, mx0, 16));
        mx1 = fmaxf(mx1, __shfl_down_sync(0xffffffffu, mx1, 16));
        mx2 = fmaxf(mx2, __shfl_down_sync(0xffffffffu, mx2, 16));
        mx3 = fmaxf(mx3, __shfl_down_sync(0xffffffffu, mx3, 16));
        if (lane < 16) {
            smm[0][wrp][lane][0] = mn0; smm[0][wrp][lane][1] = mn1;
            smm[0][wrp][lane][2] = mn2; smm[0][wrp][lane][3] = mn3;
            smm[1][wrp][lane][0] = mx0; smm[1][wrp][lane][1] = mx1;
            smm[1][wrp][lane][2] = mx2; smm[1][wrp][lane][3] = mx3;
        }
        __syncthreads();
        if (tid < IN_DIM) {
            const int g = tid >> 2, q = tid & 3;
            float a =  INFINITY, c = -INFINITY;
            #pragma unroll
            for (int w = 0; w < 8; w++) {
                a = fminf(a, smm[0][w][g][q]);
                c = fmaxf(c, smm[1][w][g][q]);
            }
            atomicMin(&g_minenc[tid], fenc(a));
            atomicMax(&g_maxenc[tid], fenc(c));
        }
    } else {
        // --- block MMB: bins (warp 0, parallel exp) + M = embed @ W^T ---
        if (wrp == 0) {
            float li = (lane < NUM_BINS) ? logits[lane] : -INFINITY;
            float m = li;
            #pragma unroll
            for (int d = 16; d >= 1; d >>= 1)
                m = fmaxf(m, __shfl_xor_sync(0xffffffffu, m, d));
            if (lane < NUM_BINS)
                sE[lane] = (float)exp((double)(li - m));  // 10 parallel exp chains
            __syncwarp();
            if (lane == 0) {
                float s = 0.f;
                #pragma unroll
                for (int i = 0; i < NUM_BINS; i++) s += sE[i];   // same order as before
                float cum = 0.f;
                #pragma unroll
                for (int i = 0; i < NUM_BINS; i++) {
                    cum += __fdiv_rn(sE[i], s);                   // IEEE div under fast-math
                    if (i < NTHRESH) g_bins[i] = cum;
                }
            }
        }
        // Stage W coalesced, store TRANSPOSED into padded smem: Wt[e][f]=W[f][e]
        #pragma unroll
        for (int i = tid; i < EMBED_DIM * EMBED_DIM; i += TPB) {
            const int f = i >> 6, e = i & 63;
            sWt[e * 65 + f] = W[i];           // read coalesced, write conflict-free
        }
        for (int i = tid; i < NUM_BINS * EMBED_DIM; i += TPB)
            sEm[i] = embed[i];
        __syncthreads();
        // M[k][f] = sum_e em[k][e] * Wt[e][f]: lane f consecutive -> no conflicts
        for (int i = tid; i < NUM_BINS * EMBED_DIM; i += TPB) {
            const int k = i >> 6, f = i & 63;
            const float* em = sEm + k * EMBED_DIM;
            float s = 0.f;
            #pragma unroll 16
            for (int e2 = 0; e2 < EMBED_DIM; e2++)
                s = fmaf(em[e2], sWt[e2 * 65 + f], s);
            g_M[i] = s;
        }
    }

    // ================= GRID BARRIER =================
    __threadfence();
    __syncthreads();
    if (tid == 0) s_ticket = atomicAdd(&g_count, 1);
    __syncthreads();

    if (s_ticket == GRID - 1) {
        __threadfence();  // acquire all atomics
        if (tid < IN_DIM) {
            unsigned emin = *(volatile unsigned*)&g_minenc[tid];
            unsigned emax = *(volatile unsigned*)&g_maxenc[tid];
            float a = fdec(emin), c = fdec(emax);
            g_mn[tid] = a;
            g_dn[tid] = (c - a) + 1e-6f;
            g_minenc[tid] = 0xFF800000u;   // reset for next graph replay
            g_maxenc[tid] = 0x007FFFFFu;
        }
        if (tid == 0) g_count = 0;
        __threadfence();
        __syncthreads();
        if (tid == 0) atomicAdd(&g_release, 1u);
    }

    if (tid == 0) {
        while (*(volatile unsigned*)&g_release == s_snap) { __nanosleep(32); }
    }
    __syncthreads();
    __threadfence();

    // ================= PHASE 2 =================
    // out[b,f] = 64*(M[0][f]+bias[f]) + sum_{k=1..9} c_k * (M[k][f]-M[k-1][f])
    // Balanced contiguous ranges: warp w -> rows [w*B/NW, (w+1)*B/NW) (9 or 10).
    const int c0 = lane * 2;
    const int c1 = c0 + 1;
    const int w  = b * 8 + wrp;

    const float mn0 = g_mn[c0], mn1 = g_mn[c1];
    const float dn0 = g_dn[c0], dn1 = g_dn[c1];

    float bins[NTHRESH];
    #pragma unroll
    for (int k = 0; k < NTHRESH; k++) bins[k] = g_bins[k];

    const float base0 = 64.f * (g_M[c0] + bias[c0]);
    const float base1 = 64.f * (g_M[c1] + bias[c1]);

    float D0[NTHRESH], D1[NTHRESH];
    #pragma unroll
    for (int k = 0; k < NTHRESH; k++) {
        D0[k] = g_M[(k + 1) * EMBED_DIM + c0] - g_M[k * EMBED_DIM + c0];
        D1[k] = g_M[(k + 1) * EMBED_DIM + c1] - g_M[k * EMBED_DIM + c1];
    }

    const float2* __restrict__ x2   = (const float2*)x;
    float2* __restrict__       out2 = (float2*)out;

    int r           = (int)(((long long)w       * BATCH) / NWARP);
    const int r_end = (int)(((long long)(w + 1) * BATCH) / NWARP);

    // ---- 4-row iterations ----
    for (; r + 4 <= r_end; r += 4) {
        const float2* xp = x2 + r * 32 + lane;
        float2 v0 = xp[0];
        float2 v1 = xp[32];
        float2 v2 = xp[64];
        float2 v3 = xp[96];

        float xa0 = __fdiv_rn(v0.x - mn0, dn0), xa1 = __fdiv_rn(v0.y - mn1, dn1);
        float xb0 = __fdiv_rn(v1.x - mn0, dn0), xb1 = __fdiv_rn(v1.y - mn1, dn1);
        float xc0 = __fdiv_rn(v2.x - mn0, dn0), xc1 = __fdiv_rn(v2.y - mn1, dn1);
        float xd0 = __fdiv_rn(v3.x - mn0, dn0), xd1 = __fdiv_rn(v3.y - mn1, dn1);

        unsigned qa0 = 0, qa1 = 0, qa2 = 0;
        unsigned qb0 = 0, qb1 = 0, qb2 = 0;
        unsigned qc0 = 0, qc1 = 0, qc2 = 0;
        unsigned qd0 = 0, qd1 = 0, qd2 = 0;
        #pragma unroll
        for (int k = 0; k < 4; k++) {
            const unsigned wgt = 1u << (8 * k);
            qa0 += (xa0 > bins[k]) ? wgt : 0u;  qa0 += (xa1 > bins[k]) ? wgt : 0u;
            qb0 += (xb0 > bins[k]) ? wgt : 0u;  qb0 += (xb1 > bins[k]) ? wgt : 0u;
            qc0 += (xc0 > bins[k]) ? wgt : 0u;  qc0 += (xc1 > bins[k]) ? wgt : 0u;
            qd0 += (xd0 > bins[k]) ? wgt : 0u;  qd0 += (xd1 > bins[k]) ? wgt : 0u;
        }
        #pragma unroll
        for (int k = 4; k < 8; k++) {
            const unsigned wgt = 1u << (8 * (k - 4));
            qa1 += (xa0 > bins[k]) ? wgt : 0u;  qa1 += (xa1 > bins[k]) ? wgt : 0u;
            qb1 += (xb0 > bins[k]) ? wgt : 0u;  qb1 += (xb1 > bins[k]) ? wgt : 0u;
            qc1 += (xc0 > bins[k]) ? wgt : 0u;  qc1 += (xc1 > bins[k]) ? wgt : 0u;
            qd1 += (xd0 > bins[k]) ? wgt : 0u;  qd1 += (xd1 > bins[k]) ? wgt : 0u;
        }
        qa2 += (xa0 > bins[8]) ? 1u : 0u;  qa2 += (xa1 > bins[8]) ? 1u : 0u;
        qb2 += (xb0 > bins[8]) ? 1u : 0u;  qb2 += (xb1 > bins[8]) ? 1u : 0u;
        qc2 += (xc0 > bins[8]) ? 1u : 0u;  qc2 += (xc1 > bins[8]) ? 1u : 0u;
        qd2 += (xd0 > bins[8]) ? 1u : 0u;  qd2 += (xd1 > bins[8]) ? 1u : 0u;

        qa0 = __reduce_add_sync(0xffffffffu, qa0);
        qa1 = __reduce_add_sync(0xffffffffu, qa1);
        qa2 = __reduce_add_sync(0xffffffffu, qa2);
        qb0 = __reduce_add_sync(0xffffffffu, qb0);
        qb1 = __reduce_add_sync(0xffffffffu, qb1);
        qb2 = __reduce_add_sync(0xffffffffu, qb2);
        qc0 = __reduce_add_sync(0xffffffffu, qc0);
        qc1 = __reduce_add_sync(0xffffffffu, qc1);
        qc2 = __reduce_add_sync(0xffffffffu, qc2);
        qd0 = __reduce_add_sync(0xffffffffu, qd0);
        qd1 = __reduce_add_sync(0xffffffffu, qd1);
        qd2 = __reduce_add_sync(0xffffffffu, qd2);

        float a0 = base0, a1 = base1, b0 = base0, b1 = base1;
        float cc0 = base0, cc1 = base1, d0 = base0, d1 = base1;
        #pragma unroll
        for (int k = 0; k < 9; k++) {
            unsigned ca = (k < 4) ? (qa0 >> (8 * k)) : ((k < 8) ? (qa1 >> (8 * (k - 4))) : qa2);
            unsigned cb = (k < 4) ? (qb0 >> (8 * k)) : ((k < 8) ? (qb1 >> (8 * (k - 4))) : qb2);
            unsigned cg = (k < 4) ? (qc0 >> (8 * k)) : ((k < 8) ? (qc1 >> (8 * (k - 4))) : qc2);
            unsigned cd = (k < 4) ? (qd0 >> (8 * k)) : ((k < 8) ? (qd1 >> (8 * (k - 4))) : qd2);
            float fa = (float)(ca & 0xffu);
            float fb = (float)(cb & 0xffu);
            float fc = (float)(cg & 0xffu);
            float fd = (float)(cd & 0xffu);
            a0  = fmaf(fa, D0[k], a0);   a1  = fmaf(fa, D1[k], a1);
            b0  = fmaf(fb, D0[k], b0);   b1  = fmaf(fb, D1[k], b1);
            cc0 = fmaf(fc, D0[k], cc0);  cc1 = fmaf(fc, D1[k], cc1);
            d0  = fmaf(fd, D0[k], d0);   d1  = fmaf(fd, D1[k], d1);
        }
        float2* op = out2 + r * 32 + lane;
        op[0]  = make_float2(a0, a1);
        op[32] = make_float2(b0, b1);
        op[64] = make_float2(cc0, cc1);
        op[96] = make_float2(d0, d1);
    }

    // ---- 1-row tail ----
    for (; r < r_end; r++) {
        float2 v0 = x2[r * 32 + lane];
        float xa0 = __fdiv_rn(v0.x - mn0, dn0), xa1 = __fdiv_rn(v0.y - mn1, dn1);
        unsigned qa0 = 0, qa1 = 0, qa2 = 0;
        #pragma unroll
        for (int k = 0; k < 4; k++) {
            const unsigned wgt = 1u << (8 * k);
            qa0 += (xa0 > bins[k]) ? wgt : 0u;  qa0 += (xa1 > bins[k]) ? wgt : 0u;
        }
        #pragma unroll
        for (int k = 4; k < 8; k++) {
            const unsigned wgt = 1u << (8 * (k - 4));
            qa1 += (xa0 > bins[k]) ? wgt : 0u;  qa1 += (xa1 > bins[k]) ? wgt : 0u;
        }
        qa2 += (xa0 > bins[8]) ? 1u : 0u;  qa2 += (xa1 > bins[8]) ? 1u : 0u;

        qa0 = __reduce_add_sync(0xffffffffu, qa0);
        qa1 = __reduce_add_sync(0xffffffffu, qa1);
        qa2 = __reduce_add_sync(0xffffffffu, qa2);

        float a0 = base0, a1 = base1;
        #pragma unroll
        for (int k = 0; k < 9; k++) {
            unsigned ca = (k < 4) ? (qa0 >> (8 * k)) : ((k < 8) ? (qa1 >> (8 * (k - 4))) : qa2);
            float fa = (float)(ca & 0xffu);
            a0 = fmaf(fa, D0[k], a0);
            a1 = fmaf(fa, D1[k], a1);
        }
        out2[r * 32 + lane] = make_float2(a0, a1);
    }
}

extern "C" void kernel_launch(void* const* d_in, const int* in_sizes, int n_in,
                              void* d_out, int out_size) {
    const float* x      = (const float*)d_in[0];
    const float* logits = (const float*)d_in[1];
    const float* embed  = (const float*)d_in[2];
    const float* W      = (const float*)d_in[3];
    const float* bias   = (const float*)d_in[4];
    float* out          = (float*)d_out;

    dybem_fused<<<GRID, TPB>>>(x, logits, embed, W, bias, out);
}